// round 7
// baseline (speedup 1.0000x reference)
#include <cuda_runtime.h>
#include <math.h>
#include <stdint.h>

#define B_   32
#define N_   512
#define C_   768
#define H_   12
#define D_   64
#define HID_ 3072
#define M_   (B_*N_)   // 16384 rows

// ---------------- scratch (device globals; no allocation allowed) ----------
__device__ float g_h1  [(size_t)M_ * C_];
__device__ float g_qkv [(size_t)M_ * 3 * C_];
__device__ float g_attn[(size_t)M_ * C_];
__device__ float g_x2  [(size_t)M_ * C_];
__device__ float g_ln2 [(size_t)M_ * C_];
__device__ float g_fc1 [(size_t)M_ * HID_];
// tf32-rounded weights: qkv_w | proj_w | fc1_w | fc2_w
#define RW_QKV 0
#define RW_PROJ (3*C_*C_)
#define RW_FC1  (RW_PROJ + C_*C_)
#define RW_FC2  (RW_FC1 + HID_*C_)
#define RW_TOT  (RW_FC2 + C_*HID_)
__device__ float g_rw[(size_t)RW_TOT];

// ================= small helpers ===========================================
__device__ __forceinline__ void cp16(uint32_t saddr, const void* g) {
    asm volatile("cp.async.cg.shared.global [%0], [%1], 16;" :: "r"(saddr), "l"(g) : "memory");
}
__device__ __forceinline__ uint32_t smem_u32(const void* p) {
    uint32_t a;
    asm("{ .reg .u64 t; cvta.to.shared.u64 t, %1; cvt.u32.u64 %0, t; }" : "=r"(a) : "l"(p));
    return a;
}
__device__ __forceinline__ uint32_t f2tf32(float f) {
    uint32_t r;
    asm("cvt.rna.tf32.f32 %0, %1;" : "=r"(r) : "f"(f));
    return r;
}
__device__ __forceinline__ float tf32r(float f) { return __uint_as_float(f2tf32(f)); }
__device__ __forceinline__ void split2(float v, uint32_t& hi, uint32_t& lo) {
    hi = f2tf32(v);
    lo = f2tf32(v - __uint_as_float(hi));
}
__device__ __forceinline__ void mma_tf32(float* c, const uint32_t* a, const uint32_t* b) {
    asm volatile("mma.sync.aligned.m16n8k8.row.col.f32.tf32.tf32.f32 "
                 "{%0,%1,%2,%3}, {%4,%5,%6,%7}, {%8,%9}, {%0,%1,%2,%3};"
                 : "+f"(c[0]), "+f"(c[1]), "+f"(c[2]), "+f"(c[3])
                 : "r"(a[0]), "r"(a[1]), "r"(a[2]), "r"(a[3]), "r"(b[0]), "r"(b[1]));
}
__device__ __forceinline__ void ldsm_x4(uint32_t* r, uint32_t addr) {
    asm volatile("ldmatrix.sync.aligned.m8n8.x4.shared.b16 {%0,%1,%2,%3}, [%4];"
                 : "=r"(r[0]), "=r"(r[1]), "=r"(r[2]), "=r"(r[3]) : "r"(addr));
}
__device__ __forceinline__ void ldsm_x2(uint32_t* r, uint32_t addr) {
    asm volatile("ldmatrix.sync.aligned.m8n8.x2.shared.b16 {%0,%1}, [%2];"
                 : "=r"(r[0]), "=r"(r[1]) : "r"(addr));
}

// ================= weight tf32 pre-round (single kernel) ===================
__global__ void __launch_bounds__(256) round_all_kernel(const float* __restrict__ w0,
                                                        const float* __restrict__ w1,
                                                        const float* __restrict__ w2,
                                                        const float* __restrict__ w3,
                                                        float* __restrict__ out)
{
    const size_t i = ((size_t)blockIdx.x * 256 + threadIdx.x) * 4;
    if (i >= (size_t)RW_TOT) return;
    const float* src;
    size_t off;
    if (i < (size_t)RW_PROJ)      { src = w0; off = i; }
    else if (i < (size_t)RW_FC1)  { src = w1; off = i - RW_PROJ; }
    else if (i < (size_t)RW_FC2)  { src = w2; off = i - RW_FC1; }
    else                          { src = w3; off = i - RW_FC2; }
    float4 v = *(const float4*)(src + off);
    v.x = tf32r(v.x); v.y = tf32r(v.y); v.z = tf32r(v.z); v.w = tf32r(v.w);
    *(float4*)(out + i) = v;
}

// ================= tf32 mma.sync GEMM ======================================
#define BKK 32
#define PAD 36
#define AS_BYTES (128 * PAD * 4)
#define STAGE_B  (2 * AS_BYTES)
#define GSMEM    (3 * STAGE_B)

template <int MODE>
__global__ void __launch_bounds__(256, 2) tc_gemm(const float* __restrict__ A,
                                                  const float* __restrict__ W,
                                                  const float* __restrict__ bias,
                                                  const float* __restrict__ res,
                                                  float* __restrict__ Cout,
                                                  int M, int Nn, int K)
{
    extern __shared__ float smem[];
    const uint32_t sbase = smem_u32(smem);
    const int tid = threadIdx.x;
    const int bm = blockIdx.y, bn = blockIdx.x;

    const float* Ab = A + (size_t)bm * 128 * K;
    const float* Wb = W + (size_t)bn * 128 * K;
    const int nk = K / BKK;

    const int lrow = tid >> 3;
    const int lch  = (tid & 7) * 4;

    auto load_stage = [&](int slot, int k0) {
        const uint32_t sA = sbase + slot * STAGE_B;
        const uint32_t sB = sA + AS_BYTES;
        #pragma unroll
        for (int p = 0; p < 4; p++) {
            const int row = lrow + p * 32;
            const uint32_t off = (uint32_t)(row * PAD + lch) * 4u;
            cp16(sA + off, Ab + (size_t)row * K + k0 + lch);
            cp16(sB + off, Wb + (size_t)row * K + k0 + lch);
        }
        asm volatile("cp.async.commit_group;" ::: "memory");
    };

    load_stage(0, 0);
    load_stage(1, BKK);

    const int wid = tid >> 5, lane = tid & 31;
    const int wm = (wid >> 2) * 64;
    const int wn = (wid & 3) * 32;
    const int qr = lane >> 2, qc = lane & 3;

    const int l7 = lane & 7;
    const int aRow = wm + l7 + ((lane >> 3) & 1) * 8;
    const int aK   = ((lane >> 4) & 1) * 4;
    const uint32_t aOff = (uint32_t)(aRow * PAD + aK) * 4u;
    const int bRow = wn + l7;
    const int bK   = ((lane >> 3) & 1) * 4;
    const uint32_t bOff = (uint32_t)(bRow * PAD + bK) * 4u;

    float acc[4][4][4];
    #pragma unroll
    for (int mi = 0; mi < 4; mi++)
        #pragma unroll
        for (int ni = 0; ni < 4; ni++)
            #pragma unroll
            for (int u = 0; u < 4; u++) acc[mi][ni][u] = 0.0f;

    int slot = 0, slot2 = 2;
    for (int i = 0; i < nk; i++) {
        if (i == nk - 1) asm volatile("cp.async.wait_group 0;" ::: "memory");
        else             asm volatile("cp.async.wait_group 1;" ::: "memory");
        __syncthreads();
        if (i + 2 < nk) load_stage(slot2, (i + 2) * BKK);

        const uint32_t sA = sbase + slot * STAGE_B;
        const uint32_t sB = sA + AS_BYTES;
        #pragma unroll
        for (int kc = 0; kc < 4; kc++) {
            uint32_t af[4][4], bf[4][2];
            #pragma unroll
            for (int mi = 0; mi < 4; mi++)
                ldsm_x4(af[mi], sA + aOff + (uint32_t)(mi * 16 * PAD * 4) + (uint32_t)(kc * 32));
            #pragma unroll
            for (int ni = 0; ni < 4; ni++)
                ldsm_x2(bf[ni], sB + bOff + (uint32_t)(ni * 8 * PAD * 4) + (uint32_t)(kc * 32));
            #pragma unroll
            for (int mi = 0; mi < 4; mi++)
                #pragma unroll
                for (int ni = 0; ni < 4; ni++)
                    mma_tf32(acc[mi][ni], af[mi], bf[ni]);
        }
        slot = (slot + 1 == 3) ? 0 : slot + 1;
        slot2 = (slot2 + 1 == 3) ? 0 : slot2 + 1;
    }

    #pragma unroll
    for (int mi = 0; mi < 4; mi++) {
        #pragma unroll
        for (int ni = 0; ni < 4; ni++) {
            const int col = bn * 128 + wn + ni * 8 + 2 * qc;
            #pragma unroll
            for (int half = 0; half < 2; half++) {
                const size_t row = (size_t)bm * 128 + wm + mi * 16 + qr + half * 8;
                float v0 = acc[mi][ni][half * 2 + 0];
                float v1 = acc[mi][ni][half * 2 + 1];
                if (MODE == 1) {
                    v0 = 2.0f * (v0 + bias[col]);
                    v1 = 2.0f * (v1 + bias[col + 1]);
                } else if (MODE == 2) {
                    v0 += bias[col];
                    v1 += bias[col + 1];
                    v0 = 0.5f * v0 * (1.0f + erff(v0 * 0.70710678118654752f));
                    v1 = 0.5f * v1 * (1.0f + erff(v1 * 0.70710678118654752f));
                    v0 = tf32r(v0);
                    v1 = tf32r(v1);
                } else if (MODE == 3) {
                    const float* rr = res + row * Nn + col;
                    v0 += bias[col] + rr[0];
                    v1 += bias[col + 1] + rr[1];
                }
                *(float2*)(Cout + row * Nn + col) = make_float2(v0, v1);
            }
        }
    }
}

// ---------------- fused LayerNorm (tf32-rounded output) --------------------
__global__ void __launch_bounds__(256) ln_kernel(const float* __restrict__ x,
                                                 const float* __restrict__ w,
                                                 const float* __restrict__ b,
                                                 float* __restrict__ out)
{
    __shared__ float red[8];
    const int row = blockIdx.x;
    const int t   = threadIdx.x;
    const float* xr = x + (size_t)row * C_;

    float v0 = xr[t], v1 = xr[t + 256], v2 = xr[t + 512];
    float s = v0 + v1 + v2;
    #pragma unroll
    for (int o = 16; o; o >>= 1) s += __shfl_xor_sync(0xffffffffu, s, o);
    if ((t & 31) == 0) red[t >> 5] = s;
    __syncthreads();
    float tot = red[0]+red[1]+red[2]+red[3]+red[4]+red[5]+red[6]+red[7];
    const float mu = tot * (1.0f / C_);

    float d0 = v0 - mu, d1 = v1 - mu, d2 = v2 - mu;
    float q = d0*d0 + d1*d1 + d2*d2;
    #pragma unroll
    for (int o = 16; o; o >>= 1) q += __shfl_xor_sync(0xffffffffu, q, o);
    __syncthreads();
    if ((t & 31) == 0) red[t >> 5] = q;
    __syncthreads();
    float var = (red[0]+red[1]+red[2]+red[3]+red[4]+red[5]+red[6]+red[7]) * (1.0f / C_);
    const float rstd = rsqrtf(var + 1e-5f);

    float* orow = out + (size_t)row * C_;
    orow[t]       = tf32r(d0 * rstd * w[t]       + b[t]);
    orow[t + 256] = tf32r(d1 * rstd * w[t + 256] + b[t + 256]);
    orow[t + 512] = tf32r(d2 * rstd * w[t + 512] + b[t + 512]);
}

// ================= flash attention, pre-split tf32 mma =====================
// 128 q-rows/block, 8 warps (16 rows each), 64-key tiles.
// All operands pre-split to (hi,lo) tf32 pairs in smem; inner loops are
// pure ldmatrix + 3x mma (hi*hi + hi*lo + lo*hi).
#define AP 68
#define OQH 0
#define OQL (128*AP)            // 8704
#define OKH (2*128*AP)          // 17408
#define OKL (OKH + 64*AP)
#define OVH (OKH + 2*64*AP)
#define OVL (OKH + 3*64*AP)
#define OPH (OKH + 4*64*AP)     // 34816
#define OPL (OPH + 128*AP)
#define ATT_SMEM ((OPL + 128*AP) * 4)   // 208896 B

__global__ void __launch_bounds__(256) attn_mma(const float* __restrict__ qkv,
                                                float* __restrict__ out)
{
    extern __shared__ float sm[];
    const uint32_t sbase = smem_u32(sm);
    float* Qh = sm + OQH;  float* Ql = sm + OQL;
    float* Kh = sm + OKH;  float* Kl = sm + OKL;
    float* Vth = sm + OVH; float* Vtl = sm + OVL;
    float* Ph = sm + OPH;  float* Pl = sm + OPL;

    const int qt = blockIdx.x;
    const int bh = blockIdx.y;
    const int h  = bh % H_;
    const int b  = bh / H_;
    const int tid = threadIdx.x;
    const int w = tid >> 5, lane = tid & 31;
    const int qr = lane >> 2, qc = lane & 3;
    const int mrow = w * 16;
    const size_t rowbase = (size_t)b * N_ + (size_t)qt * 128;

    // ldmatrix lane-address offsets
    const int l7 = lane & 7;
    const uint32_t aOff = (uint32_t)((mrow + l7 + ((lane >> 3) & 1) * 8) * AP
                                     + ((lane >> 4) & 1) * 4) * 4u;
    const uint32_t bOff = (uint32_t)(l7 * AP + ((lane >> 3) & 1) * 4) * 4u;

    // ---- load + split Q (128 x 64) ----
    #pragma unroll
    for (int t = 0; t < 8; t++) {
        int i = tid + t * 256;
        int row = i >> 4, c4 = (i & 15) * 4;
        float4 v = *(const float4*)(qkv + (rowbase + row) * (3 * C_) + h * D_ + c4);
        uint32_t h0,l0,h1,l1,h2,l2,h3,l3;
        split2(v.x, h0, l0); split2(v.y, h1, l1); split2(v.z, h2, l2); split2(v.w, h3, l3);
        *(uint4*)(Qh + row * AP + c4) = make_uint4(h0, h1, h2, h3);
        *(uint4*)(Ql + row * AP + c4) = make_uint4(l0, l1, l2, l3);
    }

    float m0 = -INFINITY, m1 = -INFINITY, l0s = 0.0f, l1s = 0.0f;
    float O[8][4];
    #pragma unroll
    for (int nt = 0; nt < 8; nt++)
        #pragma unroll
        for (int u = 0; u < 4; u++) O[nt][u] = 0.0f;

    for (int kt = 0; kt < 8; kt++) {
        __syncthreads();   // prior tile reads + (kt==0) Q writes ordering below
        // ---- load + split K (64x64), V transposed (Vt[d][key]) ----
        #pragma unroll
        for (int t = 0; t < 4; t++) {
            int i = tid + t * 256;
            int row = i >> 4, c4 = (i & 15) * 4;
            const float* src = qkv + ((size_t)b * N_ + kt * 64 + row) * (3 * C_) + C_ + h * D_ + c4;
            float4 kv = *(const float4*)src;
            float4 vv = *(const float4*)(src + C_);
            uint32_t h0,ll0,h1,ll1,h2,ll2,h3,ll3;
            split2(kv.x, h0, ll0); split2(kv.y, h1, ll1); split2(kv.z, h2, ll2); split2(kv.w, h3, ll3);
            *(uint4*)(Kh + row * AP + c4) = make_uint4(h0, h1, h2, h3);
            *(uint4*)(Kl + row * AP + c4) = make_uint4(ll0, ll1, ll2, ll3);
            split2(vv.x, h0, ll0); split2(vv.y, h1, ll1); split2(vv.z, h2, ll2); split2(vv.w, h3, ll3);
            ((uint32_t*)Vth)[(c4 + 0) * AP + row] = h0;
            ((uint32_t*)Vth)[(c4 + 1) * AP + row] = h1;
            ((uint32_t*)Vth)[(c4 + 2) * AP + row] = h2;
            ((uint32_t*)Vth)[(c4 + 3) * AP + row] = h3;
            ((uint32_t*)Vtl)[(c4 + 0) * AP + row] = ll0;
            ((uint32_t*)Vtl)[(c4 + 1) * AP + row] = ll1;
            ((uint32_t*)Vtl)[(c4 + 2) * AP + row] = ll2;
            ((uint32_t*)Vtl)[(c4 + 3) * AP + row] = ll3;
        }
        __syncthreads();

        // ---- S = Q K^T ----
        float S[8][4];
        #pragma unroll
        for (int nt = 0; nt < 8; nt++)
            #pragma unroll
            for (int u = 0; u < 4; u++) S[nt][u] = 0.0f;

        #pragma unroll
        for (int kk = 0; kk < 8; kk++) {
            uint32_t ah[4], al[4];
            ldsm_x4(ah, sbase + (uint32_t)(OQH * 4) + aOff + (uint32_t)(kk * 32));
            ldsm_x4(al, sbase + (uint32_t)(OQL * 4) + aOff + (uint32_t)(kk * 32));
            #pragma unroll
            for (int nt = 0; nt < 8; nt++) {
                uint32_t bhf[2], blf[2];
                ldsm_x2(bhf, sbase + (uint32_t)(OKH * 4) + bOff + (uint32_t)(nt * 8 * AP * 4 + kk * 32));
                ldsm_x2(blf, sbase + (uint32_t)(OKL * 4) + bOff + (uint32_t)(nt * 8 * AP * 4 + kk * 32));
                mma_tf32(S[nt], ah, bhf);
                mma_tf32(S[nt], ah, blf);
                mma_tf32(S[nt], al, bhf);
            }
        }

        // ---- online softmax ----
        float mt0 = -INFINITY, mt1 = -INFINITY;
        #pragma unroll
        for (int nt = 0; nt < 8; nt++) {
            #pragma unroll
            for (int u = 0; u < 4; u++) S[nt][u] *= 0.125f;
            mt0 = fmaxf(mt0, fmaxf(S[nt][0], S[nt][1]));
            mt1 = fmaxf(mt1, fmaxf(S[nt][2], S[nt][3]));
        }
        mt0 = fmaxf(mt0, __shfl_xor_sync(0xffffffffu, mt0, 1));
        mt0 = fmaxf(mt0, __shfl_xor_sync(0xffffffffu, mt0, 2));
        mt1 = fmaxf(mt1, __shfl_xor_sync(0xffffffffu, mt1, 1));
        mt1 = fmaxf(mt1, __shfl_xor_sync(0xffffffffu, mt1, 2));
        const float mn0 = fmaxf(m0, mt0), mn1 = fmaxf(m1, mt1);
        const float a0 = __expf(m0 - mn0), a1 = __expf(m1 - mn1);
        float ls0 = 0.0f, ls1 = 0.0f;
        #pragma unroll
        for (int nt = 0; nt < 8; nt++) {
            S[nt][0] = __expf(S[nt][0] - mn0);
            S[nt][1] = __expf(S[nt][1] - mn0);
            S[nt][2] = __expf(S[nt][2] - mn1);
            S[nt][3] = __expf(S[nt][3] - mn1);
            ls0 += S[nt][0] + S[nt][1];
            ls1 += S[nt][2] + S[nt][3];
        }
        ls0 += __shfl_xor_sync(0xffffffffu, ls0, 1);
        ls0 += __shfl_xor_sync(0xffffffffu, ls0, 2);
        ls1 += __shfl_xor_sync(0xffffffffu, ls1, 1);
        ls1 += __shfl_xor_sync(0xffffffffu, ls1, 2);
        l0s = l0s * a0 + ls0;
        l1s = l1s * a1 + ls1;
        m0 = mn0; m1 = mn1;
        #pragma unroll
        for (int nt = 0; nt < 8; nt++) {
            O[nt][0] *= a0; O[nt][1] *= a0;
            O[nt][2] *= a1; O[nt][3] *= a1;
        }

        // ---- split P in registers, store hi/lo ----
        #pragma unroll
        for (int nt = 0; nt < 8; nt++) {
            uint32_t p0h,p0l,p1h,p1l,p2h,p2l,p3h,p3l;
            split2(S[nt][0], p0h, p0l); split2(S[nt][1], p1h, p1l);
            split2(S[nt][2], p2h, p2l); split2(S[nt][3], p3h, p3l);
            *(uint2*)((uint32_t*)Ph + (mrow + qr) * AP + nt * 8 + 2 * qc)     = make_uint2(p0h, p1h);
            *(uint2*)((uint32_t*)Pl + (mrow + qr) * AP + nt * 8 + 2 * qc)     = make_uint2(p0l, p1l);
            *(uint2*)((uint32_t*)Ph + (mrow + qr + 8) * AP + nt * 8 + 2 * qc) = make_uint2(p2h, p3h);
            *(uint2*)((uint32_t*)Pl + (mrow + qr + 8) * AP + nt * 8 + 2 * qc) = make_uint2(p2l, p3l);
        }
        __syncwarp();

        // ---- O += P V ----
        #pragma unroll
        for (int kk = 0; kk < 8; kk++) {
            uint32_t ph[4], pl[4];
            ldsm_x4(ph, sbase + (uint32_t)(OPH * 4) + aOff + (uint32_t)(kk * 32));
            ldsm_x4(pl, sbase + (uint32_t)(OPL * 4) + aOff + (uint32_t)(kk * 32));
            #pragma unroll
            for (int nt = 0; nt < 8; nt++) {
                uint32_t vh[2], vl[2];
                ldsm_x2(vh, sbase + (uint32_t)(OVH * 4) + bOff + (uint32_t)(nt * 8 * AP * 4 + kk * 32));
                ldsm_x2(vl, sbase + (uint32_t)(OVL * 4) + bOff + (uint32_t)(nt * 8 * AP * 4 + kk * 32));
                mma_tf32(O[nt], ph, vh);
                mma_tf32(O[nt], ph, vl);
                mma_tf32(O[nt], pl, vh);
            }
        }
    }

    const float inv0 = 1.0f / l0s, inv1 = 1.0f / l1s;
    #pragma unroll
    for (int nt = 0; nt < 8; nt++) {
        const int col = h * D_ + nt * 8 + 2 * qc;
        const size_t r0 = rowbase + mrow + qr;
        *(float2*)(out + r0 * C_ + col) =
            make_float2(tf32r(O[nt][0] * inv0), tf32r(O[nt][1] * inv0));
        *(float2*)(out + (r0 + 8) * C_ + col) =
            make_float2(tf32r(O[nt][2] * inv1), tf32r(O[nt][3] * inv1));
    }
}

// ---------------- host launcher -------------------------------------------
extern "C" void kernel_launch(void* const* d_in, const int* in_sizes, int n_in,
                              void* d_out, int out_size)
{
    (void)in_sizes; (void)n_in; (void)out_size;
    const float* x      = (const float*)d_in[0];
    const float* ln1_w  = (const float*)d_in[1];
    const float* ln1_b  = (const float*)d_in[2];
    const float* qkv_w  = (const float*)d_in[3];
    const float* proj_w = (const float*)d_in[4];
    const float* proj_b = (const float*)d_in[5];
    const float* ln2_w  = (const float*)d_in[6];
    const float* ln2_b  = (const float*)d_in[7];
    const float* fc1_w  = (const float*)d_in[8];
    const float* fc1_b  = (const float*)d_in[9];
    const float* fc2_w  = (const float*)d_in[10];
    const float* fc2_b  = (const float*)d_in[11];
    float* out = (float*)d_out;

    float *h1, *qkvb, *attn, *x2, *ln2o, *fc1o, *rw;
    cudaGetSymbolAddress((void**)&h1,   g_h1);
    cudaGetSymbolAddress((void**)&qkvb, g_qkv);
    cudaGetSymbolAddress((void**)&attn, g_attn);
    cudaGetSymbolAddress((void**)&x2,   g_x2);
    cudaGetSymbolAddress((void**)&ln2o, g_ln2);
    cudaGetSymbolAddress((void**)&fc1o, g_fc1);
    cudaGetSymbolAddress((void**)&rw,   g_rw);

    static bool attr_done = false;
    if (!attr_done) {
        cudaFuncSetAttribute(tc_gemm<0>, cudaFuncAttributeMaxDynamicSharedMemorySize, GSMEM);
        cudaFuncSetAttribute(tc_gemm<1>, cudaFuncAttributeMaxDynamicSharedMemorySize, GSMEM);
        cudaFuncSetAttribute(tc_gemm<2>, cudaFuncAttributeMaxDynamicSharedMemorySize, GSMEM);
        cudaFuncSetAttribute(tc_gemm<3>, cudaFuncAttributeMaxDynamicSharedMemorySize, GSMEM);
        cudaFuncSetAttribute(attn_mma,   cudaFuncAttributeMaxDynamicSharedMemorySize, ATT_SMEM);
        attr_done = true;
    }

    round_all_kernel<<<(RW_TOT/4 + 255)/256, 256>>>(qkv_w, proj_w, fc1_w, fc2_w, rw);

    ln_kernel<<<M_, 256>>>(x, ln1_w, ln1_b, h1);
    tc_gemm<0><<<dim3(3*C_/128, M_/128), 256, GSMEM>>>(h1, rw + RW_QKV, nullptr, nullptr, qkvb, M_, 3*C_, C_);
    attn_mma<<<dim3(4, B_*H_), 256, ATT_SMEM>>>(qkvb, attn);
    tc_gemm<1><<<dim3(C_/128, M_/128), 256, GSMEM>>>(attn, rw + RW_PROJ, proj_b, nullptr, x2, M_, C_, C_);
    ln_kernel<<<M_, 256>>>(x2, ln2_w, ln2_b, ln2o);
    tc_gemm<2><<<dim3(HID_/128, M_/128), 256, GSMEM>>>(ln2o, rw + RW_FC1, fc1_b, nullptr, fc1o, M_, HID_, C_);
    tc_gemm<3><<<dim3(C_/128, M_/128), 256, GSMEM>>>(fc1o, rw + RW_FC2, fc2_b, x2, out, M_, C_, HID_);
}

// round 8
// speedup vs baseline: 1.0345x; 1.0345x over previous
#include <cuda_runtime.h>
#include <math.h>
#include <stdint.h>

#define B_   32
#define N_   512
#define C_   768
#define H_   12
#define D_   64
#define HID_ 3072
#define M_   (B_*N_)   // 16384 rows

// ---------------- scratch (device globals; no allocation allowed) ----------
__device__ float g_h1  [(size_t)M_ * C_];
__device__ float g_qkv [(size_t)M_ * 3 * C_];
__device__ float g_attn[(size_t)M_ * C_];
__device__ float g_x2  [(size_t)M_ * C_];
__device__ float g_ln2 [(size_t)M_ * C_];
__device__ float g_fc1 [(size_t)M_ * HID_];
// tf32-rounded weights: qkv_w | proj_w | fc1_w | fc2_w
#define RW_QKV 0
#define RW_PROJ (3*C_*C_)
#define RW_FC1  (RW_PROJ + C_*C_)
#define RW_FC2  (RW_FC1 + HID_*C_)
#define RW_TOT  (RW_FC2 + C_*HID_)
__device__ float g_rw[(size_t)RW_TOT];

// ================= small helpers ===========================================
__device__ __forceinline__ void cp16(uint32_t saddr, const void* g) {
    asm volatile("cp.async.cg.shared.global [%0], [%1], 16;" :: "r"(saddr), "l"(g) : "memory");
}
__device__ __forceinline__ uint32_t smem_u32(const void* p) {
    uint32_t a;
    asm("{ .reg .u64 t; cvta.to.shared.u64 t, %1; cvt.u32.u64 %0, t; }" : "=r"(a) : "l"(p));
    return a;
}
__device__ __forceinline__ uint32_t f2tf32(float f) {
    uint32_t r;
    asm("cvt.rna.tf32.f32 %0, %1;" : "=r"(r) : "f"(f));
    return r;
}
__device__ __forceinline__ float tf32r(float f) { return __uint_as_float(f2tf32(f)); }
__device__ __forceinline__ void split2(float v, uint32_t& hi, uint32_t& lo) {
    hi = f2tf32(v);
    lo = f2tf32(v - __uint_as_float(hi));
}
__device__ __forceinline__ void mma_tf32(float* c, const uint32_t* a, const uint32_t* b) {
    asm volatile("mma.sync.aligned.m16n8k8.row.col.f32.tf32.tf32.f32 "
                 "{%0,%1,%2,%3}, {%4,%5,%6,%7}, {%8,%9}, {%0,%1,%2,%3};"
                 : "+f"(c[0]), "+f"(c[1]), "+f"(c[2]), "+f"(c[3])
                 : "r"(a[0]), "r"(a[1]), "r"(a[2]), "r"(a[3]), "r"(b[0]), "r"(b[1]));
}
__device__ __forceinline__ void ldsm_x4(uint32_t* r, uint32_t addr) {
    asm volatile("ldmatrix.sync.aligned.m8n8.x4.shared.b16 {%0,%1,%2,%3}, [%4];"
                 : "=r"(r[0]), "=r"(r[1]), "=r"(r[2]), "=r"(r[3]) : "r"(addr));
}
__device__ __forceinline__ void ldsm_x2(uint32_t* r, uint32_t addr) {
    asm volatile("ldmatrix.sync.aligned.m8n8.x2.shared.b16 {%0,%1}, [%2];"
                 : "=r"(r[0]), "=r"(r[1]) : "r"(addr));
}

// ================= weight tf32 pre-round (single kernel) ===================
__global__ void __launch_bounds__(256) round_all_kernel(const float* __restrict__ w0,
                                                        const float* __restrict__ w1,
                                                        const float* __restrict__ w2,
                                                        const float* __restrict__ w3,
                                                        float* __restrict__ out)
{
    const size_t i = ((size_t)blockIdx.x * 256 + threadIdx.x) * 4;
    if (i >= (size_t)RW_TOT) return;
    const float* src;
    size_t off;
    if (i < (size_t)RW_PROJ)      { src = w0; off = i; }
    else if (i < (size_t)RW_FC1)  { src = w1; off = i - RW_PROJ; }
    else if (i < (size_t)RW_FC2)  { src = w2; off = i - RW_FC1; }
    else                          { src = w3; off = i - RW_FC2; }
    float4 v = *(const float4*)(src + off);
    v.x = tf32r(v.x); v.y = tf32r(v.y); v.z = tf32r(v.z); v.w = tf32r(v.w);
    *(float4*)(out + i) = v;
}

// ================= tf32 mma.sync GEMM (unchanged from R6) ==================
#define BKK 32
#define PAD 36
#define AS_BYTES (128 * PAD * 4)
#define STAGE_B  (2 * AS_BYTES)
#define GSMEM    (3 * STAGE_B)

template <int MODE>
__global__ void __launch_bounds__(256, 2) tc_gemm(const float* __restrict__ A,
                                                  const float* __restrict__ W,
                                                  const float* __restrict__ bias,
                                                  const float* __restrict__ res,
                                                  float* __restrict__ Cout,
                                                  int M, int Nn, int K)
{
    extern __shared__ float smem[];
    const uint32_t sbase = smem_u32(smem);
    const int tid = threadIdx.x;
    const int bm = blockIdx.y, bn = blockIdx.x;

    const float* Ab = A + (size_t)bm * 128 * K;
    const float* Wb = W + (size_t)bn * 128 * K;
    const int nk = K / BKK;

    const int lrow = tid >> 3;
    const int lch  = (tid & 7) * 4;

    auto load_stage = [&](int slot, int k0) {
        const uint32_t sA = sbase + slot * STAGE_B;
        const uint32_t sB = sA + AS_BYTES;
        #pragma unroll
        for (int p = 0; p < 4; p++) {
            const int row = lrow + p * 32;
            const uint32_t off = (uint32_t)(row * PAD + lch) * 4u;
            cp16(sA + off, Ab + (size_t)row * K + k0 + lch);
            cp16(sB + off, Wb + (size_t)row * K + k0 + lch);
        }
        asm volatile("cp.async.commit_group;" ::: "memory");
    };

    load_stage(0, 0);
    load_stage(1, BKK);

    const int wid = tid >> 5, lane = tid & 31;
    const int wm = (wid >> 2) * 64;
    const int wn = (wid & 3) * 32;
    const int qr = lane >> 2, qc = lane & 3;

    const int l7 = lane & 7;
    const int aRow = wm + l7 + ((lane >> 3) & 1) * 8;
    const int aK   = ((lane >> 4) & 1) * 4;
    const uint32_t aOff = (uint32_t)(aRow * PAD + aK) * 4u;
    const int bRow = wn + l7;
    const int bK   = ((lane >> 3) & 1) * 4;
    const uint32_t bOff = (uint32_t)(bRow * PAD + bK) * 4u;

    float acc[4][4][4];
    #pragma unroll
    for (int mi = 0; mi < 4; mi++)
        #pragma unroll
        for (int ni = 0; ni < 4; ni++)
            #pragma unroll
            for (int u = 0; u < 4; u++) acc[mi][ni][u] = 0.0f;

    int slot = 0, slot2 = 2;
    for (int i = 0; i < nk; i++) {
        if (i == nk - 1) asm volatile("cp.async.wait_group 0;" ::: "memory");
        else             asm volatile("cp.async.wait_group 1;" ::: "memory");
        __syncthreads();
        if (i + 2 < nk) load_stage(slot2, (i + 2) * BKK);

        const uint32_t sA = sbase + slot * STAGE_B;
        const uint32_t sB = sA + AS_BYTES;
        #pragma unroll
        for (int kc = 0; kc < 4; kc++) {
            uint32_t af[4][4], bf[4][2];
            #pragma unroll
            for (int mi = 0; mi < 4; mi++)
                ldsm_x4(af[mi], sA + aOff + (uint32_t)(mi * 16 * PAD * 4) + (uint32_t)(kc * 32));
            #pragma unroll
            for (int ni = 0; ni < 4; ni++)
                ldsm_x2(bf[ni], sB + bOff + (uint32_t)(ni * 8 * PAD * 4) + (uint32_t)(kc * 32));
            #pragma unroll
            for (int mi = 0; mi < 4; mi++)
                #pragma unroll
                for (int ni = 0; ni < 4; ni++)
                    mma_tf32(acc[mi][ni], af[mi], bf[ni]);
        }
        slot = (slot + 1 == 3) ? 0 : slot + 1;
        slot2 = (slot2 + 1 == 3) ? 0 : slot2 + 1;
    }

    #pragma unroll
    for (int mi = 0; mi < 4; mi++) {
        #pragma unroll
        for (int ni = 0; ni < 4; ni++) {
            const int col = bn * 128 + wn + ni * 8 + 2 * qc;
            #pragma unroll
            for (int half = 0; half < 2; half++) {
                const size_t row = (size_t)bm * 128 + wm + mi * 16 + qr + half * 8;
                float v0 = acc[mi][ni][half * 2 + 0];
                float v1 = acc[mi][ni][half * 2 + 1];
                if (MODE == 1) {
                    v0 = 2.0f * (v0 + bias[col]);
                    v1 = 2.0f * (v1 + bias[col + 1]);
                } else if (MODE == 2) {
                    v0 += bias[col];
                    v1 += bias[col + 1];
                    v0 = 0.5f * v0 * (1.0f + erff(v0 * 0.70710678118654752f));
                    v1 = 0.5f * v1 * (1.0f + erff(v1 * 0.70710678118654752f));
                    v0 = tf32r(v0);
                    v1 = tf32r(v1);
                } else if (MODE == 3) {
                    const float* rr = res + row * Nn + col;
                    v0 += bias[col] + rr[0];
                    v1 += bias[col + 1] + rr[1];
                }
                *(float2*)(Cout + row * Nn + col) = make_float2(v0, v1);
            }
        }
    }
}

// ---------------- fused LayerNorm (tf32-rounded output) --------------------
__global__ void __launch_bounds__(256) ln_kernel(const float* __restrict__ x,
                                                 const float* __restrict__ w,
                                                 const float* __restrict__ b,
                                                 float* __restrict__ out)
{
    __shared__ float red[8];
    const int row = blockIdx.x;
    const int t   = threadIdx.x;
    const float* xr = x + (size_t)row * C_;

    float v0 = xr[t], v1 = xr[t + 256], v2 = xr[t + 512];
    float s = v0 + v1 + v2;
    #pragma unroll
    for (int o = 16; o; o >>= 1) s += __shfl_xor_sync(0xffffffffu, s, o);
    if ((t & 31) == 0) red[t >> 5] = s;
    __syncthreads();
    float tot = red[0]+red[1]+red[2]+red[3]+red[4]+red[5]+red[6]+red[7];
    const float mu = tot * (1.0f / C_);

    float d0 = v0 - mu, d1 = v1 - mu, d2 = v2 - mu;
    float q = d0*d0 + d1*d1 + d2*d2;
    #pragma unroll
    for (int o = 16; o; o >>= 1) q += __shfl_xor_sync(0xffffffffu, q, o);
    __syncthreads();
    if ((t & 31) == 0) red[t >> 5] = q;
    __syncthreads();
    float var = (red[0]+red[1]+red[2]+red[3]+red[4]+red[5]+red[6]+red[7]) * (1.0f / C_);
    const float rstd = rsqrtf(var + 1e-5f);

    float* orow = out + (size_t)row * C_;
    orow[t]       = tf32r(d0 * rstd * w[t]       + b[t]);
    orow[t + 256] = tf32r(d1 * rstd * w[t + 256] + b[t + 256]);
    orow[t + 512] = tf32r(d2 * rstd * w[t + 512] + b[t + 512]);
}

// ================= flash attention v3: reg-shuffle P, 2 CTA/SM =============
// 128 q-rows/block, 8 warps (16 rows each), 64-key tiles.
// Q stored fp32 (split per kk), K/V stored pre-split (hi/lo), P converted
// from S accumulator fragments to A-fragments via intra-quad shuffles.
#define AP 68
#define OQ  0
#define OKH (128*AP)            // 8704
#define OKL (OKH + 64*AP)
#define OVH (OKH + 2*64*AP)
#define OVL (OKH + 3*64*AP)
#define ATT_SMEM ((OKH + 4*64*AP) * 4)   // 104448 B

__global__ void __launch_bounds__(256, 2) attn_mma(const float* __restrict__ qkv,
                                                   float* __restrict__ out)
{
    extern __shared__ float sm[];
    const uint32_t sbase = smem_u32(sm);
    float* Qs = sm + OQ;
    float* Kh = sm + OKH;  float* Kl = sm + OKL;
    float* Vth = sm + OVH; float* Vtl = sm + OVL;

    const int qt = blockIdx.x;
    const int bh = blockIdx.y;
    const int h  = bh % H_;
    const int b  = bh / H_;
    const int tid = threadIdx.x;
    const int w = tid >> 5, lane = tid & 31;
    const int qr = lane >> 2, qc = lane & 3;
    const int mrow = w * 16;
    const size_t rowbase = (size_t)b * N_ + (size_t)qt * 128;

    const int l7 = lane & 7;
    const uint32_t aOff = (uint32_t)((mrow + l7 + ((lane >> 3) & 1) * 8) * AP
                                     + ((lane >> 4) & 1) * 4) * 4u;
    const uint32_t bOff = (uint32_t)(l7 * AP + ((lane >> 3) & 1) * 4) * 4u;
    const int src0 = (lane & ~3) | (qc >> 1);   // quad lane holding cols {qc}
    const int src1 = src0 + 2;                  // quad lane holding cols {qc+4}

    // ---- stage Q (128 x 64, fp32) ----
    #pragma unroll
    for (int t = 0; t < 8; t++) {
        int i = tid + t * 256;
        int row = i >> 4, c4 = (i & 15) * 4;
        float4 v = *(const float4*)(qkv + (rowbase + row) * (3 * C_) + h * D_ + c4);
        *(float4*)(Qs + row * AP + c4) = v;
    }

    float m0 = -INFINITY, m1 = -INFINITY, l0s = 0.0f, l1s = 0.0f;
    float O[8][4];
    #pragma unroll
    for (int nt = 0; nt < 8; nt++)
        #pragma unroll
        for (int u = 0; u < 4; u++) O[nt][u] = 0.0f;

    for (int kt = 0; kt < 8; kt++) {
        __syncthreads();
        // ---- load + split K (64x64) and V transposed (Vt[d][key]) ----
        #pragma unroll
        for (int t = 0; t < 4; t++) {
            int i = tid + t * 256;
            int row = i >> 4, c4 = (i & 15) * 4;
            const float* src = qkv + ((size_t)b * N_ + kt * 64 + row) * (3 * C_) + C_ + h * D_ + c4;
            float4 kv = *(const float4*)src;
            float4 vv = *(const float4*)(src + C_);
            uint32_t h0,ll0,h1,ll1,h2,ll2,h3,ll3;
            split2(kv.x, h0, ll0); split2(kv.y, h1, ll1); split2(kv.z, h2, ll2); split2(kv.w, h3, ll3);
            *(uint4*)(Kh + row * AP + c4) = make_uint4(h0, h1, h2, h3);
            *(uint4*)(Kl + row * AP + c4) = make_uint4(ll0, ll1, ll2, ll3);
            split2(vv.x, h0, ll0); split2(vv.y, h1, ll1); split2(vv.z, h2, ll2); split2(vv.w, h3, ll3);
            ((uint32_t*)Vth)[(c4 + 0) * AP + row] = h0;
            ((uint32_t*)Vth)[(c4 + 1) * AP + row] = h1;
            ((uint32_t*)Vth)[(c4 + 2) * AP + row] = h2;
            ((uint32_t*)Vth)[(c4 + 3) * AP + row] = h3;
            ((uint32_t*)Vtl)[(c4 + 0) * AP + row] = ll0;
            ((uint32_t*)Vtl)[(c4 + 1) * AP + row] = ll1;
            ((uint32_t*)Vtl)[(c4 + 2) * AP + row] = ll2;
            ((uint32_t*)Vtl)[(c4 + 3) * AP + row] = ll3;
        }
        __syncthreads();

        // ---- S = Q K^T ----
        float S[8][4];
        #pragma unroll
        for (int nt = 0; nt < 8; nt++)
            #pragma unroll
            for (int u = 0; u < 4; u++) S[nt][u] = 0.0f;

        #pragma unroll
        for (int kk = 0; kk < 8; kk++) {
            uint32_t aq[4], ah[4], al[4];
            ldsm_x4(aq, sbase + aOff + (uint32_t)(kk * 32));
            #pragma unroll
            for (int u = 0; u < 4; u++) split2(__uint_as_float(aq[u]), ah[u], al[u]);
            #pragma unroll
            for (int nt = 0; nt < 8; nt++) {
                uint32_t bhf[2], blf[2];
                ldsm_x2(bhf, sbase + (uint32_t)(OKH * 4) + bOff + (uint32_t)(nt * 8 * AP * 4 + kk * 32));
                ldsm_x2(blf, sbase + (uint32_t)(OKL * 4) + bOff + (uint32_t)(nt * 8 * AP * 4 + kk * 32));
                mma_tf32(S[nt], ah, bhf);
                mma_tf32(S[nt], ah, blf);
                mma_tf32(S[nt], al, bhf);
            }
        }

        // ---- online softmax ----
        float mt0 = -INFINITY, mt1 = -INFINITY;
        #pragma unroll
        for (int nt = 0; nt < 8; nt++) {
            #pragma unroll
            for (int u = 0; u < 4; u++) S[nt][u] *= 0.125f;
            mt0 = fmaxf(mt0, fmaxf(S[nt][0], S[nt][1]));
            mt1 = fmaxf(mt1, fmaxf(S[nt][2], S[nt][3]));
        }
        mt0 = fmaxf(mt0, __shfl_xor_sync(0xffffffffu, mt0, 1));
        mt0 = fmaxf(mt0, __shfl_xor_sync(0xffffffffu, mt0, 2));
        mt1 = fmaxf(mt1, __shfl_xor_sync(0xffffffffu, mt1, 1));
        mt1 = fmaxf(mt1, __shfl_xor_sync(0xffffffffu, mt1, 2));
        const float mn0 = fmaxf(m0, mt0), mn1 = fmaxf(m1, mt1);
        const float a0 = __expf(m0 - mn0), a1 = __expf(m1 - mn1);
        float ls0 = 0.0f, ls1 = 0.0f;
        #pragma unroll
        for (int nt = 0; nt < 8; nt++) {
            S[nt][0] = __expf(S[nt][0] - mn0);
            S[nt][1] = __expf(S[nt][1] - mn0);
            S[nt][2] = __expf(S[nt][2] - mn1);
            S[nt][3] = __expf(S[nt][3] - mn1);
            ls0 += S[nt][0] + S[nt][1];
            ls1 += S[nt][2] + S[nt][3];
        }
        ls0 += __shfl_xor_sync(0xffffffffu, ls0, 1);
        ls0 += __shfl_xor_sync(0xffffffffu, ls0, 2);
        ls1 += __shfl_xor_sync(0xffffffffu, ls1, 1);
        ls1 += __shfl_xor_sync(0xffffffffu, ls1, 2);
        l0s = l0s * a0 + ls0;
        l1s = l1s * a1 + ls1;
        m0 = mn0; m1 = mn1;
        #pragma unroll
        for (int nt = 0; nt < 8; nt++) {
            O[nt][0] *= a0; O[nt][1] *= a0;
            O[nt][2] *= a1; O[nt][3] *= a1;
        }

        // ---- O += P V: P fragments via quad shuffles of S[kk] ----
        #pragma unroll
        for (int kk = 0; kk < 8; kk++) {
            const float v00 = __shfl_sync(0xffffffffu, S[kk][0], src0);
            const float v01 = __shfl_sync(0xffffffffu, S[kk][1], src0);
            const float v10 = __shfl_sync(0xffffffffu, S[kk][2], src0);
            const float v11 = __shfl_sync(0xffffffffu, S[kk][3], src0);
            const float w00 = __shfl_sync(0xffffffffu, S[kk][0], src1);
            const float w01 = __shfl_sync(0xffffffffu, S[kk][1], src1);
            const float w10 = __shfl_sync(0xffffffffu, S[kk][2], src1);
            const float w11 = __shfl_sync(0xffffffffu, S[kk][3], src1);
            const float a0f = (qc & 1) ? v01 : v00;   // P(qr,   kk*8+qc)
            const float a1f = (qc & 1) ? v11 : v10;   // P(qr+8, kk*8+qc)
            const float a2f = (qc & 1) ? w01 : w00;   // P(qr,   kk*8+qc+4)
            const float a3f = (qc & 1) ? w11 : w10;   // P(qr+8, kk*8+qc+4)
            uint32_t ph[4], pl[4];
            split2(a0f, ph[0], pl[0]);
            split2(a1f, ph[1], pl[1]);
            split2(a2f, ph[2], pl[2]);
            split2(a3f, ph[3], pl[3]);
            #pragma unroll
            for (int nt = 0; nt < 8; nt++) {
                uint32_t vh[2], vl[2];
                ldsm_x2(vh, sbase + (uint32_t)(OVH * 4) + bOff + (uint32_t)(nt * 8 * AP * 4 + kk * 32));
                ldsm_x2(vl, sbase + (uint32_t)(OVL * 4) + bOff + (uint32_t)(nt * 8 * AP * 4 + kk * 32));
                mma_tf32(O[nt], ph, vh);
                mma_tf32(O[nt], ph, vl);
                mma_tf32(O[nt], pl, vh);
            }
        }
    }

    const float inv0 = 1.0f / l0s, inv1 = 1.0f / l1s;
    #pragma unroll
    for (int nt = 0; nt < 8; nt++) {
        const int col = h * D_ + nt * 8 + 2 * qc;
        const size_t r0 = rowbase + mrow + qr;
        *(float2*)(out + r0 * C_ + col) =
            make_float2(tf32r(O[nt][0] * inv0), tf32r(O[nt][1] * inv0));
        *(float2*)(out + (r0 + 8) * C_ + col) =
            make_float2(tf32r(O[nt][2] * inv1), tf32r(O[nt][3] * inv1));
    }
}

// ---------------- host launcher -------------------------------------------
extern "C" void kernel_launch(void* const* d_in, const int* in_sizes, int n_in,
                              void* d_out, int out_size)
{
    (void)in_sizes; (void)n_in; (void)out_size;
    const float* x      = (const float*)d_in[0];
    const float* ln1_w  = (const float*)d_in[1];
    const float* ln1_b  = (const float*)d_in[2];
    const float* qkv_w  = (const float*)d_in[3];
    const float* proj_w = (const float*)d_in[4];
    const float* proj_b = (const float*)d_in[5];
    const float* ln2_w  = (const float*)d_in[6];
    const float* ln2_b  = (const float*)d_in[7];
    const float* fc1_w  = (const float*)d_in[8];
    const float* fc1_b  = (const float*)d_in[9];
    const float* fc2_w  = (const float*)d_in[10];
    const float* fc2_b  = (const float*)d_in[11];
    float* out = (float*)d_out;

    float *h1, *qkvb, *attn, *x2, *ln2o, *fc1o, *rw;
    cudaGetSymbolAddress((void**)&h1,   g_h1);
    cudaGetSymbolAddress((void**)&qkvb, g_qkv);
    cudaGetSymbolAddress((void**)&attn, g_attn);
    cudaGetSymbolAddress((void**)&x2,   g_x2);
    cudaGetSymbolAddress((void**)&ln2o, g_ln2);
    cudaGetSymbolAddress((void**)&fc1o, g_fc1);
    cudaGetSymbolAddress((void**)&rw,   g_rw);

    static bool attr_done = false;
    if (!attr_done) {
        cudaFuncSetAttribute(tc_gemm<0>, cudaFuncAttributeMaxDynamicSharedMemorySize, GSMEM);
        cudaFuncSetAttribute(tc_gemm<1>, cudaFuncAttributeMaxDynamicSharedMemorySize, GSMEM);
        cudaFuncSetAttribute(tc_gemm<2>, cudaFuncAttributeMaxDynamicSharedMemorySize, GSMEM);
        cudaFuncSetAttribute(tc_gemm<3>, cudaFuncAttributeMaxDynamicSharedMemorySize, GSMEM);
        cudaFuncSetAttribute(attn_mma,   cudaFuncAttributeMaxDynamicSharedMemorySize, ATT_SMEM);
        attr_done = true;
    }

    round_all_kernel<<<(RW_TOT/4 + 255)/256, 256>>>(qkv_w, proj_w, fc1_w, fc2_w, rw);

    ln_kernel<<<M_, 256>>>(x, ln1_w, ln1_b, h1);
    tc_gemm<0><<<dim3(3*C_/128, M_/128), 256, GSMEM>>>(h1, rw + RW_QKV, nullptr, nullptr, qkvb, M_, 3*C_, C_);
    attn_mma<<<dim3(4, B_*H_), 256, ATT_SMEM>>>(qkvb, attn);
    tc_gemm<1><<<dim3(C_/128, M_/128), 256, GSMEM>>>(attn, rw + RW_PROJ, proj_b, nullptr, x2, M_, C_, C_);
    ln_kernel<<<M_, 256>>>(x2, ln2_w, ln2_b, ln2o);
    tc_gemm<2><<<dim3(HID_/128, M_/128), 256, GSMEM>>>(ln2o, rw + RW_FC1, fc1_b, nullptr, fc1o, M_, HID_, C_);
    tc_gemm<3><<<dim3(C_/128, M_/128), 256, GSMEM>>>(fc1o, rw + RW_FC2, fc2_b, x2, out, M_, C_, HID_);
}

// round 9
// speedup vs baseline: 1.0596x; 1.0243x over previous
#include <cuda_runtime.h>
#include <math.h>
#include <stdint.h>

#define B_   32
#define N_   512
#define C_   768
#define H_   12
#define D_   64
#define HID_ 3072
#define M_   (B_*N_)   // 16384 rows

// ---------------- scratch (device globals; no allocation allowed) ----------
__device__ float g_h1  [(size_t)M_ * C_];
__device__ float g_qkv [(size_t)M_ * 3 * C_];
__device__ float g_attn[(size_t)M_ * C_];
__device__ float g_x2  [(size_t)M_ * C_];
__device__ float g_ln2 [(size_t)M_ * C_];
__device__ float g_fc1 [(size_t)M_ * HID_];
// tf32-rounded weights: qkv_w | proj_w | fc1_w | fc2_w
#define RW_QKV 0
#define RW_PROJ (3*C_*C_)
#define RW_FC1  (RW_PROJ + C_*C_)
#define RW_FC2  (RW_FC1 + HID_*C_)
#define RW_TOT  (RW_FC2 + C_*HID_)
__device__ float g_rw[(size_t)RW_TOT];

// ================= small helpers ===========================================
__device__ __forceinline__ void cp16(uint32_t saddr, const void* g) {
    asm volatile("cp.async.cg.shared.global [%0], [%1], 16;" :: "r"(saddr), "l"(g) : "memory");
}
__device__ __forceinline__ uint32_t smem_u32(const void* p) {
    uint32_t a;
    asm("{ .reg .u64 t; cvta.to.shared.u64 t, %1; cvt.u32.u64 %0, t; }" : "=r"(a) : "l"(p));
    return a;
}
__device__ __forceinline__ uint32_t f2tf32(float f) {
    uint32_t r;
    asm("cvt.rna.tf32.f32 %0, %1;" : "=r"(r) : "f"(f));
    return r;
}
__device__ __forceinline__ float tf32r(float f) { return __uint_as_float(f2tf32(f)); }
__device__ __forceinline__ void split2(float v, uint32_t& hi, uint32_t& lo) {
    hi = f2tf32(v);
    lo = f2tf32(v - __uint_as_float(hi));
}
__device__ __forceinline__ void mma_tf32(float* c, const uint32_t* a, const uint32_t* b) {
    asm volatile("mma.sync.aligned.m16n8k8.row.col.f32.tf32.tf32.f32 "
                 "{%0,%1,%2,%3}, {%4,%5,%6,%7}, {%8,%9}, {%0,%1,%2,%3};"
                 : "+f"(c[0]), "+f"(c[1]), "+f"(c[2]), "+f"(c[3])
                 : "r"(a[0]), "r"(a[1]), "r"(a[2]), "r"(a[3]), "r"(b[0]), "r"(b[1]));
}
__device__ __forceinline__ void ldsm_x4(uint32_t* r, uint32_t addr) {
    asm volatile("ldmatrix.sync.aligned.m8n8.x4.shared.b16 {%0,%1,%2,%3}, [%4];"
                 : "=r"(r[0]), "=r"(r[1]), "=r"(r[2]), "=r"(r[3]) : "r"(addr));
}

// ================= weight tf32 pre-round (single kernel) ===================
__global__ void __launch_bounds__(256) round_all_kernel(const float* __restrict__ w0,
                                                        const float* __restrict__ w1,
                                                        const float* __restrict__ w2,
                                                        const float* __restrict__ w3,
                                                        float* __restrict__ out)
{
    const size_t i = ((size_t)blockIdx.x * 256 + threadIdx.x) * 4;
    if (i >= (size_t)RW_TOT) return;
    const float* src;
    size_t off;
    if (i < (size_t)RW_PROJ)      { src = w0; off = i; }
    else if (i < (size_t)RW_FC1)  { src = w1; off = i - RW_PROJ; }
    else if (i < (size_t)RW_FC2)  { src = w2; off = i - RW_FC1; }
    else                          { src = w3; off = i - RW_FC2; }
    float4 v = *(const float4*)(src + off);
    v.x = tf32r(v.x); v.y = tf32r(v.y); v.z = tf32r(v.z); v.w = tf32r(v.w);
    *(float4*)(out + i) = v;
}

// ================= tf32 mma.sync GEMM ======================================
// x4 ldmatrix for both A and B fragments (B: two nt tiles per instruction).
#define BKK 32
#define PAD 36
#define AS_BYTES (128 * PAD * 4)
#define STAGE_B  (2 * AS_BYTES)
#define GSMEM    (3 * STAGE_B)

template <int MODE>
__global__ void __launch_bounds__(256, 2) tc_gemm(const float* __restrict__ A,
                                                  const float* __restrict__ W,
                                                  const float* __restrict__ bias,
                                                  const float* __restrict__ res,
                                                  float* __restrict__ Cout,
                                                  int M, int Nn, int K)
{
    extern __shared__ float smem[];
    const uint32_t sbase = smem_u32(smem);
    const int tid = threadIdx.x;
    const int bm = blockIdx.y, bn = blockIdx.x;

    const float* Ab = A + (size_t)bm * 128 * K;
    const float* Wb = W + (size_t)bn * 128 * K;
    const int nk = K / BKK;

    const int lrow = tid >> 3;
    const int lch  = (tid & 7) * 4;

    auto load_stage = [&](int slot, int k0) {
        const uint32_t sA = sbase + slot * STAGE_B;
        const uint32_t sB = sA + AS_BYTES;
        #pragma unroll
        for (int p = 0; p < 4; p++) {
            const int row = lrow + p * 32;
            const uint32_t off = (uint32_t)(row * PAD + lch) * 4u;
            cp16(sA + off, Ab + (size_t)row * K + k0 + lch);
            cp16(sB + off, Wb + (size_t)row * K + k0 + lch);
        }
        asm volatile("cp.async.commit_group;" ::: "memory");
    };

    load_stage(0, 0);
    load_stage(1, BKK);

    const int wid = tid >> 5, lane = tid & 31;
    const int wm = (wid >> 2) * 64;
    const int wn = (wid & 3) * 32;
    const int qr = lane >> 2, qc = lane & 3;

    const int l7 = lane & 7;
    const uint32_t aOff = (uint32_t)((wm + l7 + ((lane >> 3) & 1) * 8) * PAD
                                     + ((lane >> 4) & 1) * 4) * 4u;
    // x4 B: lanes 0-15 -> nt tile rows (k lo/hi), lanes 16-31 -> nt+1 tile rows
    const uint32_t bOff4 = (uint32_t)((wn + l7 + ((lane >> 4) & 1) * 8) * PAD
                                      + ((lane >> 3) & 1) * 4) * 4u;

    float acc[4][4][4];
    #pragma unroll
    for (int mi = 0; mi < 4; mi++)
        #pragma unroll
        for (int ni = 0; ni < 4; ni++)
            #pragma unroll
            for (int u = 0; u < 4; u++) acc[mi][ni][u] = 0.0f;

    int slot = 0, slot2 = 2;
    for (int i = 0; i < nk; i++) {
        if (i == nk - 1) asm volatile("cp.async.wait_group 0;" ::: "memory");
        else             asm volatile("cp.async.wait_group 1;" ::: "memory");
        __syncthreads();
        if (i + 2 < nk) load_stage(slot2, (i + 2) * BKK);

        const uint32_t sA = sbase + slot * STAGE_B;
        const uint32_t sB = sA + AS_BYTES;
        #pragma unroll
        for (int kc = 0; kc < 4; kc++) {
            uint32_t af[4][4], bf[2][4];
            #pragma unroll
            for (int mi = 0; mi < 4; mi++)
                ldsm_x4(af[mi], sA + aOff + (uint32_t)(mi * 16 * PAD * 4) + (uint32_t)(kc * 32));
            #pragma unroll
            for (int np = 0; np < 2; np++)
                ldsm_x4(bf[np], sB + bOff4 + (uint32_t)(np * 16 * PAD * 4) + (uint32_t)(kc * 32));
            #pragma unroll
            for (int mi = 0; mi < 4; mi++)
                #pragma unroll
                for (int ni = 0; ni < 4; ni++)
                    mma_tf32(acc[mi][ni], af[mi], &bf[ni >> 1][(ni & 1) * 2]);
        }
        slot = (slot + 1 == 3) ? 0 : slot + 1;
        slot2 = (slot2 + 1 == 3) ? 0 : slot2 + 1;
    }

    #pragma unroll
    for (int mi = 0; mi < 4; mi++) {
        #pragma unroll
        for (int ni = 0; ni < 4; ni++) {
            const int col = bn * 128 + wn + ni * 8 + 2 * qc;
            #pragma unroll
            for (int half = 0; half < 2; half++) {
                const size_t row = (size_t)bm * 128 + wm + mi * 16 + qr + half * 8;
                float v0 = acc[mi][ni][half * 2 + 0];
                float v1 = acc[mi][ni][half * 2 + 1];
                if (MODE == 1) {
                    v0 = 2.0f * (v0 + bias[col]);
                    v1 = 2.0f * (v1 + bias[col + 1]);
                } else if (MODE == 2) {
                    v0 += bias[col];
                    v1 += bias[col + 1];
                    v0 = 0.5f * v0 * (1.0f + erff(v0 * 0.70710678118654752f));
                    v1 = 0.5f * v1 * (1.0f + erff(v1 * 0.70710678118654752f));
                    v0 = tf32r(v0);
                    v1 = tf32r(v1);
                } else if (MODE == 3) {
                    const float* rr = res + row * Nn + col;
                    v0 += bias[col] + rr[0];
                    v1 += bias[col + 1] + rr[1];
                }
                *(float2*)(Cout + row * Nn + col) = make_float2(v0, v1);
            }
        }
    }
}

// ---------------- fused LayerNorm (tf32-rounded output) --------------------
__global__ void __launch_bounds__(256) ln_kernel(const float* __restrict__ x,
                                                 const float* __restrict__ w,
                                                 const float* __restrict__ b,
                                                 float* __restrict__ out)
{
    __shared__ float red[8];
    const int row = blockIdx.x;
    const int t   = threadIdx.x;
    const float* xr = x + (size_t)row * C_;

    float v0 = xr[t], v1 = xr[t + 256], v2 = xr[t + 512];
    float s = v0 + v1 + v2;
    #pragma unroll
    for (int o = 16; o; o >>= 1) s += __shfl_xor_sync(0xffffffffu, s, o);
    if ((t & 31) == 0) red[t >> 5] = s;
    __syncthreads();
    float tot = red[0]+red[1]+red[2]+red[3]+red[4]+red[5]+red[6]+red[7];
    const float mu = tot * (1.0f / C_);

    float d0 = v0 - mu, d1 = v1 - mu, d2 = v2 - mu;
    float q = d0*d0 + d1*d1 + d2*d2;
    #pragma unroll
    for (int o = 16; o; o >>= 1) q += __shfl_xor_sync(0xffffffffu, q, o);
    __syncthreads();
    if ((t & 31) == 0) red[t >> 5] = q;
    __syncthreads();
    float var = (red[0]+red[1]+red[2]+red[3]+red[4]+red[5]+red[6]+red[7]) * (1.0f / C_);
    const float rstd = rsqrtf(var + 1e-5f);

    float* orow = out + (size_t)row * C_;
    orow[t]       = tf32r(d0 * rstd * w[t]       + b[t]);
    orow[t + 256] = tf32r(d1 * rstd * w[t + 256] + b[t + 256]);
    orow[t + 512] = tf32r(d2 * rstd * w[t + 512] + b[t + 512]);
}

// ================= flash attention v4: x4 fragment loads ===================
#define AP 68
#define OQ  0
#define OKH (128*AP)
#define OKL (OKH + 64*AP)
#define OVH (OKH + 2*64*AP)
#define OVL (OKH + 3*64*AP)
#define ATT_SMEM ((OKH + 4*64*AP) * 4)   // 104448 B

__global__ void __launch_bounds__(256, 2) attn_mma(const float* __restrict__ qkv,
                                                   float* __restrict__ out)
{
    extern __shared__ float sm[];
    const uint32_t sbase = smem_u32(sm);
    float* Qs = sm + OQ;
    float* Kh = sm + OKH;  float* Kl = sm + OKL;
    float* Vth = sm + OVH; float* Vtl = sm + OVL;

    const int qt = blockIdx.x;
    const int bh = blockIdx.y;
    const int h  = bh % H_;
    const int b  = bh / H_;
    const int tid = threadIdx.x;
    const int w = tid >> 5, lane = tid & 31;
    const int qr = lane >> 2, qc = lane & 3;
    const int mrow = w * 16;
    const size_t rowbase = (size_t)b * N_ + (size_t)qt * 128;

    const int l7 = lane & 7;
    const uint32_t aOff = (uint32_t)((mrow + l7 + ((lane >> 3) & 1) * 8) * AP
                                     + ((lane >> 4) & 1) * 4) * 4u;
    const uint32_t bOff4 = (uint32_t)((l7 + ((lane >> 4) & 1) * 8) * AP
                                      + ((lane >> 3) & 1) * 4) * 4u;
    const int src0 = (lane & ~3) | (qc >> 1);
    const int src1 = src0 + 2;

    // ---- stage Q (128 x 64, fp32) ----
    #pragma unroll
    for (int t = 0; t < 8; t++) {
        int i = tid + t * 256;
        int row = i >> 4, c4 = (i & 15) * 4;
        float4 v = *(const float4*)(qkv + (rowbase + row) * (3 * C_) + h * D_ + c4);
        *(float4*)(Qs + row * AP + c4) = v;
    }

    float m0 = -INFINITY, m1 = -INFINITY, l0s = 0.0f, l1s = 0.0f;
    float O[8][4];
    #pragma unroll
    for (int nt = 0; nt < 8; nt++)
        #pragma unroll
        for (int u = 0; u < 4; u++) O[nt][u] = 0.0f;

    for (int kt = 0; kt < 8; kt++) {
        __syncthreads();
        // ---- load + split K (64x64) and V transposed ----
        #pragma unroll
        for (int t = 0; t < 4; t++) {
            int i = tid + t * 256;
            int row = i >> 4, c4 = (i & 15) * 4;
            const float* src = qkv + ((size_t)b * N_ + kt * 64 + row) * (3 * C_) + C_ + h * D_ + c4;
            float4 kv = *(const float4*)src;
            float4 vv = *(const float4*)(src + C_);
            uint32_t h0,ll0,h1,ll1,h2,ll2,h3,ll3;
            split2(kv.x, h0, ll0); split2(kv.y, h1, ll1); split2(kv.z, h2, ll2); split2(kv.w, h3, ll3);
            *(uint4*)(Kh + row * AP + c4) = make_uint4(h0, h1, h2, h3);
            *(uint4*)(Kl + row * AP + c4) = make_uint4(ll0, ll1, ll2, ll3);
            split2(vv.x, h0, ll0); split2(vv.y, h1, ll1); split2(vv.z, h2, ll2); split2(vv.w, h3, ll3);
            ((uint32_t*)Vth)[(c4 + 0) * AP + row] = h0;
            ((uint32_t*)Vth)[(c4 + 1) * AP + row] = h1;
            ((uint32_t*)Vth)[(c4 + 2) * AP + row] = h2;
            ((uint32_t*)Vth)[(c4 + 3) * AP + row] = h3;
            ((uint32_t*)Vtl)[(c4 + 0) * AP + row] = ll0;
            ((uint32_t*)Vtl)[(c4 + 1) * AP + row] = ll1;
            ((uint32_t*)Vtl)[(c4 + 2) * AP + row] = ll2;
            ((uint32_t*)Vtl)[(c4 + 3) * AP + row] = ll3;
        }
        __syncthreads();

        // ---- S = Q K^T ----
        float S[8][4];
        #pragma unroll
        for (int nt = 0; nt < 8; nt++)
            #pragma unroll
            for (int u = 0; u < 4; u++) S[nt][u] = 0.0f;

        #pragma unroll
        for (int kk = 0; kk < 8; kk++) {
            uint32_t aq[4], ah[4], al[4];
            ldsm_x4(aq, sbase + aOff + (uint32_t)(kk * 32));
            #pragma unroll
            for (int u = 0; u < 4; u++) split2(__uint_as_float(aq[u]), ah[u], al[u]);
            #pragma unroll
            for (int np = 0; np < 4; np++) {
                uint32_t kh4[4], kl4[4];
                ldsm_x4(kh4, sbase + (uint32_t)(OKH * 4) + bOff4 + (uint32_t)(np * 16 * AP * 4 + kk * 32));
                ldsm_x4(kl4, sbase + (uint32_t)(OKL * 4) + bOff4 + (uint32_t)(np * 16 * AP * 4 + kk * 32));
                mma_tf32(S[2*np],   ah, kh4);
                mma_tf32(S[2*np],   ah, kl4);
                mma_tf32(S[2*np],   al, kh4);
                mma_tf32(S[2*np+1], ah, kh4 + 2);
                mma_tf32(S[2*np+1], ah, kl4 + 2);
                mma_tf32(S[2*np+1], al, kh4 + 2);
            }
        }

        // ---- online softmax ----
        float mt0 = -INFINITY, mt1 = -INFINITY;
        #pragma unroll
        for (int nt = 0; nt < 8; nt++) {
            #pragma unroll
            for (int u = 0; u < 4; u++) S[nt][u] *= 0.125f;
            mt0 = fmaxf(mt0, fmaxf(S[nt][0], S[nt][1]));
            mt1 = fmaxf(mt1, fmaxf(S[nt][2], S[nt][3]));
        }
        mt0 = fmaxf(mt0, __shfl_xor_sync(0xffffffffu, mt0, 1));
        mt0 = fmaxf(mt0, __shfl_xor_sync(0xffffffffu, mt0, 2));
        mt1 = fmaxf(mt1, __shfl_xor_sync(0xffffffffu, mt1, 1));
        mt1 = fmaxf(mt1, __shfl_xor_sync(0xffffffffu, mt1, 2));
        const float mn0 = fmaxf(m0, mt0), mn1 = fmaxf(m1, mt1);
        const float a0 = __expf(m0 - mn0), a1 = __expf(m1 - mn1);
        float ls0 = 0.0f, ls1 = 0.0f;
        #pragma unroll
        for (int nt = 0; nt < 8; nt++) {
            S[nt][0] = __expf(S[nt][0] - mn0);
            S[nt][1] = __expf(S[nt][1] - mn0);
            S[nt][2] = __expf(S[nt][2] - mn1);
            S[nt][3] = __expf(S[nt][3] - mn1);
            ls0 += S[nt][0] + S[nt][1];
            ls1 += S[nt][2] + S[nt][3];
        }
        ls0 += __shfl_xor_sync(0xffffffffu, ls0, 1);
        ls0 += __shfl_xor_sync(0xffffffffu, ls0, 2);
        ls1 += __shfl_xor_sync(0xffffffffu, ls1, 1);
        ls1 += __shfl_xor_sync(0xffffffffu, ls1, 2);
        l0s = l0s * a0 + ls0;
        l1s = l1s * a1 + ls1;
        m0 = mn0; m1 = mn1;
        #pragma unroll
        for (int nt = 0; nt < 8; nt++) {
            O[nt][0] *= a0; O[nt][1] *= a0;
            O[nt][2] *= a1; O[nt][3] *= a1;
        }

        // ---- O += P V: P fragments via quad shuffles of S[kk] ----
        #pragma unroll
        for (int kk = 0; kk < 8; kk++) {
            const float v00 = __shfl_sync(0xffffffffu, S[kk][0], src0);
            const float v01 = __shfl_sync(0xffffffffu, S[kk][1], src0);
            const float v10 = __shfl_sync(0xffffffffu, S[kk][2], src0);
            const float v11 = __shfl_sync(0xffffffffu, S[kk][3], src0);
            const float w00 = __shfl_sync(0xffffffffu, S[kk][0], src1);
            const float w01 = __shfl_sync(0xffffffffu, S[kk][1], src1);
            const float w10 = __shfl_sync(0xffffffffu, S[kk][2], src1);
            const float w11 = __shfl_sync(0xffffffffu, S[kk][3], src1);
            const float a0f = (qc & 1) ? v01 : v00;
            const float a1f = (qc & 1) ? v11 : v10;
            const float a2f = (qc & 1) ? w01 : w00;
            const float a3f = (qc & 1) ? w11 : w10;
            uint32_t ph[4], pl[4];
            split2(a0f, ph[0], pl[0]);
            split2(a1f, ph[1], pl[1]);
            split2(a2f, ph[2], pl[2]);
            split2(a3f, ph[3], pl[3]);
            #pragma unroll
            for (int np = 0; np < 4; np++) {
                uint32_t vh4[4], vl4[4];
                ldsm_x4(vh4, sbase + (uint32_t)(OVH * 4) + bOff4 + (uint32_t)(np * 16 * AP * 4 + kk * 32));
                ldsm_x4(vl4, sbase + (uint32_t)(OVL * 4) + bOff4 + (uint32_t)(np * 16 * AP * 4 + kk * 32));
                mma_tf32(O[2*np],   ph, vh4);
                mma_tf32(O[2*np],   ph, vl4);
                mma_tf32(O[2*np],   pl, vh4);
                mma_tf32(O[2*np+1], ph, vh4 + 2);
                mma_tf32(O[2*np+1], ph, vl4 + 2);
                mma_tf32(O[2*np+1], pl, vh4 + 2);
            }
        }
    }

    const float inv0 = 1.0f / l0s, inv1 = 1.0f / l1s;
    #pragma unroll
    for (int nt = 0; nt < 8; nt++) {
        const int col = h * D_ + nt * 8 + 2 * qc;
        const size_t r0 = rowbase + mrow + qr;
        *(float2*)(out + r0 * C_ + col) =
            make_float2(tf32r(O[nt][0] * inv0), tf32r(O[nt][1] * inv0));
        *(float2*)(out + (r0 + 8) * C_ + col) =
            make_float2(tf32r(O[nt][2] * inv1), tf32r(O[nt][3] * inv1));
    }
}

// ---------------- host launcher -------------------------------------------
extern "C" void kernel_launch(void* const* d_in, const int* in_sizes, int n_in,
                              void* d_out, int out_size)
{
    (void)in_sizes; (void)n_in; (void)out_size;
    const float* x      = (const float*)d_in[0];
    const float* ln1_w  = (const float*)d_in[1];
    const float* ln1_b  = (const float*)d_in[2];
    const float* qkv_w  = (const float*)d_in[3];
    const float* proj_w = (const float*)d_in[4];
    const float* proj_b = (const float*)d_in[5];
    const float* ln2_w  = (const float*)d_in[6];
    const float* ln2_b  = (const float*)d_in[7];
    const float* fc1_w  = (const float*)d_in[8];
    const float* fc1_b  = (const float*)d_in[9];
    const float* fc2_w  = (const float*)d_in[10];
    const float* fc2_b  = (const float*)d_in[11];
    float* out = (float*)d_out;

    float *h1, *qkvb, *attn, *x2, *ln2o, *fc1o, *rw;
    cudaGetSymbolAddress((void**)&h1,   g_h1);
    cudaGetSymbolAddress((void**)&qkvb, g_qkv);
    cudaGetSymbolAddress((void**)&attn, g_attn);
    cudaGetSymbolAddress((void**)&x2,   g_x2);
    cudaGetSymbolAddress((void**)&ln2o, g_ln2);
    cudaGetSymbolAddress((void**)&fc1o, g_fc1);
    cudaGetSymbolAddress((void**)&rw,   g_rw);

    static bool attr_done = false;
    if (!attr_done) {
        cudaFuncSetAttribute(tc_gemm<0>, cudaFuncAttributeMaxDynamicSharedMemorySize, GSMEM);
        cudaFuncSetAttribute(tc_gemm<1>, cudaFuncAttributeMaxDynamicSharedMemorySize, GSMEM);
        cudaFuncSetAttribute(tc_gemm<2>, cudaFuncAttributeMaxDynamicSharedMemorySize, GSMEM);
        cudaFuncSetAttribute(tc_gemm<3>, cudaFuncAttributeMaxDynamicSharedMemorySize, GSMEM);
        cudaFuncSetAttribute(attn_mma,   cudaFuncAttributeMaxDynamicSharedMemorySize, ATT_SMEM);
        attr_done = true;
    }

    round_all_kernel<<<(RW_TOT/4 + 255)/256, 256>>>(qkv_w, proj_w, fc1_w, fc2_w, rw);

    ln_kernel<<<M_, 256>>>(x, ln1_w, ln1_b, h1);
    tc_gemm<0><<<dim3(3*C_/128, M_/128), 256, GSMEM>>>(h1, rw + RW_QKV, nullptr, nullptr, qkvb, M_, 3*C_, C_);
    attn_mma<<<dim3(4, B_*H_), 256, ATT_SMEM>>>(qkvb, attn);
    tc_gemm<1><<<dim3(C_/128, M_/128), 256, GSMEM>>>(attn, rw + RW_PROJ, proj_b, nullptr, x2, M_, C_, C_);
    ln_kernel<<<M_, 256>>>(x2, ln2_w, ln2_b, ln2o);
    tc_gemm<2><<<dim3(HID_/128, M_/128), 256, GSMEM>>>(ln2o, rw + RW_FC1, fc1_b, nullptr, fc1o, M_, HID_, C_);
    tc_gemm<3><<<dim3(C_/128, M_/128), 256, GSMEM>>>(fc1o, rw + RW_FC2, fc2_b, x2, out, M_, C_, HID_);
}

// round 11
// speedup vs baseline: 1.1519x; 1.0871x over previous
#include <cuda_runtime.h>
#include <math.h>
#include <stdint.h>

#define B_   32
#define N_   512
#define C_   768
#define H_   12
#define D_   64
#define HID_ 3072
#define M_   (B_*N_)   // 16384 rows

// ---------------- scratch (device globals; no allocation allowed) ----------
__device__ float g_h1  [(size_t)M_ * C_];
__device__ float g_qkv [(size_t)M_ * 3 * C_];
__device__ float g_attn[(size_t)M_ * C_];
__device__ float g_x2  [(size_t)M_ * C_];
__device__ float g_ln2 [(size_t)M_ * C_];
__device__ float g_fc1 [(size_t)M_ * HID_];
// tf32-rounded weights: qkv_w | proj_w | fc1_w | fc2_w
#define RW_QKV 0
#define RW_PROJ (3*C_*C_)
#define RW_FC1  (RW_PROJ + C_*C_)
#define RW_FC2  (RW_FC1 + HID_*C_)
#define RW_TOT  (RW_FC2 + C_*HID_)
__device__ float g_rw[(size_t)RW_TOT];

// ================= small helpers ===========================================
__device__ __forceinline__ void cp16(uint32_t saddr, const void* g) {
    asm volatile("cp.async.cg.shared.global [%0], [%1], 16;" :: "r"(saddr), "l"(g) : "memory");
}
__device__ __forceinline__ uint32_t smem_u32(const void* p) {
    uint32_t a;
    asm("{ .reg .u64 t; cvta.to.shared.u64 t, %1; cvt.u32.u64 %0, t; }" : "=r"(a) : "l"(p));
    return a;
}
__device__ __forceinline__ uint32_t f2tf32(float f) {
    uint32_t r;
    asm("cvt.rna.tf32.f32 %0, %1;" : "=r"(r) : "f"(f));
    return r;
}
__device__ __forceinline__ float tf32r(float f) { return __uint_as_float(f2tf32(f)); }
__device__ __forceinline__ void split2(float v, uint32_t& hi, uint32_t& lo) {
    hi = f2tf32(v);
    lo = f2tf32(v - __uint_as_float(hi));
}
__device__ __forceinline__ void mma_tf32(float* c, const uint32_t* a, const uint32_t* b) {
    asm volatile("mma.sync.aligned.m16n8k8.row.col.f32.tf32.tf32.f32 "
                 "{%0,%1,%2,%3}, {%4,%5,%6,%7}, {%8,%9}, {%0,%1,%2,%3};"
                 : "+f"(c[0]), "+f"(c[1]), "+f"(c[2]), "+f"(c[3])
                 : "r"(a[0]), "r"(a[1]), "r"(a[2]), "r"(a[3]), "r"(b[0]), "r"(b[1]));
}
__device__ __forceinline__ void ldsm_x4(uint32_t* r, uint32_t addr) {
    asm volatile("ldmatrix.sync.aligned.m8n8.x4.shared.b16 {%0,%1,%2,%3}, [%4];"
                 : "=r"(r[0]), "=r"(r[1]), "=r"(r[2]), "=r"(r[3]) : "r"(addr));
}

// ================= weight tf32 pre-round (single kernel) ===================
__global__ void __launch_bounds__(256) round_all_kernel(const float* __restrict__ w0,
                                                        const float* __restrict__ w1,
                                                        const float* __restrict__ w2,
                                                        const float* __restrict__ w3,
                                                        float* __restrict__ out)
{
    const size_t i = ((size_t)blockIdx.x * 256 + threadIdx.x) * 4;
    if (i >= (size_t)RW_TOT) return;
    const float* src;
    size_t off;
    if (i < (size_t)RW_PROJ)      { src = w0; off = i; }
    else if (i < (size_t)RW_FC1)  { src = w1; off = i - RW_PROJ; }
    else if (i < (size_t)RW_FC2)  { src = w2; off = i - RW_FC1; }
    else                          { src = w3; off = i - RW_FC2; }
    float4 v = *(const float4*)(src + off);
    v.x = tf32r(v.x); v.y = tf32r(v.y); v.z = tf32r(v.z); v.w = tf32r(v.w);
    *(float4*)(out + i) = v;
}

// ================= tf32 mma.sync GEMM ======================================
#define BKK 32
#define PAD 36
#define AS_BYTES (128 * PAD * 4)
#define STAGE_B  (2 * AS_BYTES)
#define GSMEM    (3 * STAGE_B)

template <int MODE>
__global__ void __launch_bounds__(256, 2) tc_gemm(const float* __restrict__ A,
                                                  const float* __restrict__ W,
                                                  const float* __restrict__ bias,
                                                  const float* __restrict__ res,
                                                  float* __restrict__ Cout,
                                                  int M, int Nn, int K)
{
    extern __shared__ float smem[];
    const uint32_t sbase = smem_u32(smem);
    const int tid = threadIdx.x;
    const int bm = blockIdx.y, bn = blockIdx.x;

    const float* Ab = A + (size_t)bm * 128 * K;
    const float* Wb = W + (size_t)bn * 128 * K;
    const int nk = K / BKK;

    const int lrow = tid >> 3;
    const int lch  = (tid & 7) * 4;

    auto load_stage = [&](int slot, int k0) {
        const uint32_t sA = sbase + slot * STAGE_B;
        const uint32_t sB = sA + AS_BYTES;
        #pragma unroll
        for (int p = 0; p < 4; p++) {
            const int row = lrow + p * 32;
            const uint32_t off = (uint32_t)(row * PAD + lch) * 4u;
            cp16(sA + off, Ab + (size_t)row * K + k0 + lch);
            cp16(sB + off, Wb + (size_t)row * K + k0 + lch);
        }
        asm volatile("cp.async.commit_group;" ::: "memory");
    };

    load_stage(0, 0);
    load_stage(1, BKK);

    const int wid = tid >> 5, lane = tid & 31;
    const int wm = (wid >> 2) * 64;
    const int wn = (wid & 3) * 32;
    const int qr = lane >> 2, qc = lane & 3;

    const int l7 = lane & 7;
    const uint32_t aOff = (uint32_t)((wm + l7 + ((lane >> 3) & 1) * 8) * PAD
                                     + ((lane >> 4) & 1) * 4) * 4u;
    const uint32_t bOff4 = (uint32_t)((wn + l7 + ((lane >> 4) & 1) * 8) * PAD
                                      + ((lane >> 3) & 1) * 4) * 4u;

    float acc[4][4][4];
    #pragma unroll
    for (int mi = 0; mi < 4; mi++)
        #pragma unroll
        for (int ni = 0; ni < 4; ni++)
            #pragma unroll
            for (int u = 0; u < 4; u++) acc[mi][ni][u] = 0.0f;

    int slot = 0, slot2 = 2;
    for (int i = 0; i < nk; i++) {
        if (i == nk - 1) asm volatile("cp.async.wait_group 0;" ::: "memory");
        else             asm volatile("cp.async.wait_group 1;" ::: "memory");
        __syncthreads();
        if (i + 2 < nk) load_stage(slot2, (i + 2) * BKK);

        const uint32_t sA = sbase + slot * STAGE_B;
        const uint32_t sB = sA + AS_BYTES;
        #pragma unroll
        for (int kc = 0; kc < 4; kc++) {
            uint32_t af[4][4], bf[2][4];
            #pragma unroll
            for (int mi = 0; mi < 4; mi++)
                ldsm_x4(af[mi], sA + aOff + (uint32_t)(mi * 16 * PAD * 4) + (uint32_t)(kc * 32));
            #pragma unroll
            for (int np = 0; np < 2; np++)
                ldsm_x4(bf[np], sB + bOff4 + (uint32_t)(np * 16 * PAD * 4) + (uint32_t)(kc * 32));
            #pragma unroll
            for (int mi = 0; mi < 4; mi++)
                #pragma unroll
                for (int ni = 0; ni < 4; ni++)
                    mma_tf32(acc[mi][ni], af[mi], &bf[ni >> 1][(ni & 1) * 2]);
        }
        slot = (slot + 1 == 3) ? 0 : slot + 1;
        slot2 = (slot2 + 1 == 3) ? 0 : slot2 + 1;
    }

    #pragma unroll
    for (int mi = 0; mi < 4; mi++) {
        #pragma unroll
        for (int ni = 0; ni < 4; ni++) {
            const int col = bn * 128 + wn + ni * 8 + 2 * qc;
            #pragma unroll
            for (int half = 0; half < 2; half++) {
                const size_t row = (size_t)bm * 128 + wm + mi * 16 + qr + half * 8;
                float v0 = acc[mi][ni][half * 2 + 0];
                float v1 = acc[mi][ni][half * 2 + 1];
                if (MODE == 1) {
                    v0 = 2.0f * (v0 + bias[col]);
                    v1 = 2.0f * (v1 + bias[col + 1]);
                } else if (MODE == 2) {
                    v0 += bias[col];
                    v1 += bias[col + 1];
                    v0 = 0.5f * v0 * (1.0f + erff(v0 * 0.70710678118654752f));
                    v1 = 0.5f * v1 * (1.0f + erff(v1 * 0.70710678118654752f));
                    v0 = tf32r(v0);
                    v1 = tf32r(v1);
                } else if (MODE == 3) {
                    const float* rr = res + row * Nn + col;
                    v0 += bias[col] + rr[0];
                    v1 += bias[col + 1] + rr[1];
                }
                *(float2*)(Cout + row * Nn + col) = make_float2(v0, v1);
            }
        }
    }
}

// ---------------- fused LayerNorm (tf32-rounded output) --------------------
__global__ void __launch_bounds__(256) ln_kernel(const float* __restrict__ x,
                                                 const float* __restrict__ w,
                                                 const float* __restrict__ b,
                                                 float* __restrict__ out)
{
    __shared__ float red[8];
    const int row = blockIdx.x;
    const int t   = threadIdx.x;
    const float* xr = x + (size_t)row * C_;

    float v0 = xr[t], v1 = xr[t + 256], v2 = xr[t + 512];
    float s = v0 + v1 + v2;
    #pragma unroll
    for (int o = 16; o; o >>= 1) s += __shfl_xor_sync(0xffffffffu, s, o);
    if ((t & 31) == 0) red[t >> 5] = s;
    __syncthreads();
    float tot = red[0]+red[1]+red[2]+red[3]+red[4]+red[5]+red[6]+red[7];
    const float mu = tot * (1.0f / C_);

    float d0 = v0 - mu, d1 = v1 - mu, d2 = v2 - mu;
    float q = d0*d0 + d1*d1 + d2*d2;
    #pragma unroll
    for (int o = 16; o; o >>= 1) q += __shfl_xor_sync(0xffffffffu, q, o);
    __syncthreads();
    if ((t & 31) == 0) red[t >> 5] = q;
    __syncthreads();
    float var = (red[0]+red[1]+red[2]+red[3]+red[4]+red[5]+red[6]+red[7]) * (1.0f / C_);
    const float rstd = rsqrtf(var + 1e-5f);

    float* orow = out + (size_t)row * C_;
    orow[t]       = tf32r(d0 * rstd * w[t]       + b[t]);
    orow[t + 256] = tf32r(d1 * rstd * w[t + 256] + b[t + 256]);
    orow[t + 512] = tf32r(d2 * rstd * w[t + 512] + b[t + 512]);
}

// ================= flash attention v5: split-A-only tf32 ===================
// S = (Qh+Ql)*Kh,  O += (Ph+Pl)*Vh.  K/V stored hi-only (tf32-rounded).
#define AP 68
#define OQ  0
#define OKH (128*AP)                // 8704
#define OVH (OKH + 64*AP)           // 13056
#define ATT_SMEM ((OKH + 2*64*AP) * 4)   // 69632 B

__global__ void __launch_bounds__(256, 2) attn_mma(const float* __restrict__ qkv,
                                                   float* __restrict__ out)
{
    extern __shared__ float sm[];
    const uint32_t sbase = smem_u32(sm);
    float* Qs = sm + OQ;
    float* Kh = sm + OKH;
    float* Vth = sm + OVH;

    const int qt = blockIdx.x;
    const int bh = blockIdx.y;
    const int h  = bh % H_;
    const int b  = bh / H_;
    const int tid = threadIdx.x;
    const int w = tid >> 5, lane = tid & 31;
    const int qr = lane >> 2, qc = lane & 3;
    const int mrow = w * 16;
    const size_t rowbase = (size_t)b * N_ + (size_t)qt * 128;

    const int l7 = lane & 7;
    const uint32_t aOff = (uint32_t)((mrow + l7 + ((lane >> 3) & 1) * 8) * AP
                                     + ((lane >> 4) & 1) * 4) * 4u;
    const uint32_t bOff4 = (uint32_t)((l7 + ((lane >> 4) & 1) * 8) * AP
                                      + ((lane >> 3) & 1) * 4) * 4u;
    const int src0 = (lane & ~3) | (qc >> 1);
    const int src1 = src0 + 2;

    // ---- stage Q (128 x 64, fp32) ----
    #pragma unroll
    for (int t = 0; t < 8; t++) {
        int i = tid + t * 256;
        int row = i >> 4, c4 = (i & 15) * 4;
        float4 v = *(const float4*)(qkv + (rowbase + row) * (3 * C_) + h * D_ + c4);
        *(float4*)(Qs + row * AP + c4) = v;
    }

    float m0 = -INFINITY, m1 = -INFINITY, l0s = 0.0f, l1s = 0.0f;
    float O[8][4];
    #pragma unroll
    for (int nt = 0; nt < 8; nt++)
        #pragma unroll
        for (int u = 0; u < 4; u++) O[nt][u] = 0.0f;

    for (int kt = 0; kt < 8; kt++) {
        __syncthreads();
        // ---- load K (hi only) and V transposed (hi only) ----
        #pragma unroll
        for (int t = 0; t < 4; t++) {
            int i = tid + t * 256;
            int row = i >> 4, c4 = (i & 15) * 4;
            const float* src = qkv + ((size_t)b * N_ + kt * 64 + row) * (3 * C_) + C_ + h * D_ + c4;
            float4 kv = *(const float4*)src;
            float4 vv = *(const float4*)(src + C_);
            *(uint4*)(Kh + row * AP + c4) =
                make_uint4(f2tf32(kv.x), f2tf32(kv.y), f2tf32(kv.z), f2tf32(kv.w));
            ((uint32_t*)Vth)[(c4 + 0) * AP + row] = f2tf32(vv.x);
            ((uint32_t*)Vth)[(c4 + 1) * AP + row] = f2tf32(vv.y);
            ((uint32_t*)Vth)[(c4 + 2) * AP + row] = f2tf32(vv.z);
            ((uint32_t*)Vth)[(c4 + 3) * AP + row] = f2tf32(vv.w);
        }
        __syncthreads();

        // ---- S = (Qh+Ql) Kh^T ----
        float S[8][4];
        #pragma unroll
        for (int nt = 0; nt < 8; nt++)
            #pragma unroll
            for (int u = 0; u < 4; u++) S[nt][u] = 0.0f;

        #pragma unroll
        for (int kk = 0; kk < 8; kk++) {
            uint32_t aq[4], ah[4], al[4];
            ldsm_x4(aq, sbase + aOff + (uint32_t)(kk * 32));
            #pragma unroll
            for (int u = 0; u < 4; u++) split2(__uint_as_float(aq[u]), ah[u], al[u]);
            #pragma unroll
            for (int np = 0; np < 4; np++) {
                uint32_t kh4[4];
                ldsm_x4(kh4, sbase + (uint32_t)(OKH * 4) + bOff4 + (uint32_t)(np * 16 * AP * 4 + kk * 32));
                mma_tf32(S[2*np],   ah, kh4);
                mma_tf32(S[2*np],   al, kh4);
                mma_tf32(S[2*np+1], ah, kh4 + 2);
                mma_tf32(S[2*np+1], al, kh4 + 2);
            }
        }

        // ---- online softmax ----
        float mt0 = -INFINITY, mt1 = -INFINITY;
        #pragma unroll
        for (int nt = 0; nt < 8; nt++) {
            #pragma unroll
            for (int u = 0; u < 4; u++) S[nt][u] *= 0.125f;
            mt0 = fmaxf(mt0, fmaxf(S[nt][0], S[nt][1]));
            mt1 = fmaxf(mt1, fmaxf(S[nt][2], S[nt][3]));
        }
        mt0 = fmaxf(mt0, __shfl_xor_sync(0xffffffffu, mt0, 1));
        mt0 = fmaxf(mt0, __shfl_xor_sync(0xffffffffu, mt0, 2));
        mt1 = fmaxf(mt1, __shfl_xor_sync(0xffffffffu, mt1, 1));
        mt1 = fmaxf(mt1, __shfl_xor_sync(0xffffffffu, mt1, 2));
        const float mn0 = fmaxf(m0, mt0), mn1 = fmaxf(m1, mt1);
        const float a0 = __expf(m0 - mn0), a1 = __expf(m1 - mn1);
        float ls0 = 0.0f, ls1 = 0.0f;
        #pragma unroll
        for (int nt = 0; nt < 8; nt++) {
            S[nt][0] = __expf(S[nt][0] - mn0);
            S[nt][1] = __expf(S[nt][1] - mn0);
            S[nt][2] = __expf(S[nt][2] - mn1);
            S[nt][3] = __expf(S[nt][3] - mn1);
            ls0 += S[nt][0] + S[nt][1];
            ls1 += S[nt][2] + S[nt][3];
        }
        ls0 += __shfl_xor_sync(0xffffffffu, ls0, 1);
        ls0 += __shfl_xor_sync(0xffffffffu, ls0, 2);
        ls1 += __shfl_xor_sync(0xffffffffu, ls1, 1);
        ls1 += __shfl_xor_sync(0xffffffffu, ls1, 2);
        l0s = l0s * a0 + ls0;
        l1s = l1s * a1 + ls1;
        m0 = mn0; m1 = mn1;
        #pragma unroll
        for (int nt = 0; nt < 8; nt++) {
            O[nt][0] *= a0; O[nt][1] *= a0;
            O[nt][2] *= a1; O[nt][3] *= a1;
        }

        // ---- O += (Ph+Pl) Vh: P fragments via quad shuffles of S[kk] ----
        #pragma unroll
        for (int kk = 0; kk < 8; kk++) {
            const float v00 = __shfl_sync(0xffffffffu, S[kk][0], src0);
            const float v01 = __shfl_sync(0xffffffffu, S[kk][1], src0);
            const float v10 = __shfl_sync(0xffffffffu, S[kk][2], src0);
            const float v11 = __shfl_sync(0xffffffffu, S[kk][3], src0);
            const float w00 = __shfl_sync(0xffffffffu, S[kk][0], src1);
            const float w01 = __shfl_sync(0xffffffffu, S[kk][1], src1);
            const float w10 = __shfl_sync(0xffffffffu, S[kk][2], src1);
            const float w11 = __shfl_sync(0xffffffffu, S[kk][3], src1);
            const float a0f = (qc & 1) ? v01 : v00;
            const float a1f = (qc & 1) ? v11 : v10;
            const float a2f = (qc & 1) ? w01 : w00;
            const float a3f = (qc & 1) ? w11 : w10;
            uint32_t ph[4], pl[4];
            split2(a0f, ph[0], pl[0]);
            split2(a1f, ph[1], pl[1]);
            split2(a2f, ph[2], pl[2]);
            split2(a3f, ph[3], pl[3]);
            #pragma unroll
            for (int np = 0; np < 4; np++) {
                uint32_t vh4[4];
                ldsm_x4(vh4, sbase + (uint32_t)(OVH * 4) + bOff4 + (uint32_t)(np * 16 * AP * 4 + kk * 32));
                mma_tf32(O[2*np],   ph, vh4);
                mma_tf32(O[2*np],   pl, vh4);
                mma_tf32(O[2*np+1], ph, vh4 + 2);
                mma_tf32(O[2*np+1], pl, vh4 + 2);
            }
        }
    }

    const float inv0 = 1.0f / l0s, inv1 = 1.0f / l1s;
    #pragma unroll
    for (int nt = 0; nt < 8; nt++) {
        const int col = h * D_ + nt * 8 + 2 * qc;
        const size_t r0 = rowbase + mrow + qr;
        *(float2*)(out + r0 * C_ + col) =
            make_float2(tf32r(O[nt][0] * inv0), tf32r(O[nt][1] * inv0));
        *(float2*)(out + (r0 + 8) * C_ + col) =
            make_float2(tf32r(O[nt][2] * inv1), tf32r(O[nt][3] * inv1));
    }
}

// ---------------- host launcher -------------------------------------------
extern "C" void kernel_launch(void* const* d_in, const int* in_sizes, int n_in,
                              void* d_out, int out_size)
{
    (void)in_sizes; (void)n_in; (void)out_size;
    const float* x      = (const float*)d_in[0];
    const float* ln1_w  = (const float*)d_in[1];
    const float* ln1_b  = (const float*)d_in[2];
    const float* qkv_w  = (const float*)d_in[3];
    const float* proj_w = (const float*)d_in[4];
    const float* proj_b = (const float*)d_in[5];
    const float* ln2_w  = (const float*)d_in[6];
    const float* ln2_b  = (const float*)d_in[7];
    const float* fc1_w  = (const float*)d_in[8];
    const float* fc1_b  = (const float*)d_in[9];
    const float* fc2_w  = (const float*)d_in[10];
    const float* fc2_b  = (const float*)d_in[11];
    float* out = (float*)d_out;

    float *h1, *qkvb, *attn, *x2, *ln2o, *fc1o, *rw;
    cudaGetSymbolAddress((void**)&h1,   g_h1);
    cudaGetSymbolAddress((void**)&qkvb, g_qkv);
    cudaGetSymbolAddress((void**)&attn, g_attn);
    cudaGetSymbolAddress((void**)&x2,   g_x2);
    cudaGetSymbolAddress((void**)&ln2o, g_ln2);
    cudaGetSymbolAddress((void**)&fc1o, g_fc1);
    cudaGetSymbolAddress((void**)&rw,   g_rw);

    static bool attr_done = false;
    if (!attr_done) {
        cudaFuncSetAttribute(tc_gemm<0>, cudaFuncAttributeMaxDynamicSharedMemorySize, GSMEM);
        cudaFuncSetAttribute(tc_gemm<1>, cudaFuncAttributeMaxDynamicSharedMemorySize, GSMEM);
        cudaFuncSetAttribute(tc_gemm<2>, cudaFuncAttributeMaxDynamicSharedMemorySize, GSMEM);
        cudaFuncSetAttribute(tc_gemm<3>, cudaFuncAttributeMaxDynamicSharedMemorySize, GSMEM);
        cudaFuncSetAttribute(attn_mma,   cudaFuncAttributeMaxDynamicSharedMemorySize, ATT_SMEM);
        attr_done = true;
    }

    round_all_kernel<<<(RW_TOT/4 + 255)/256, 256>>>(qkv_w, proj_w, fc1_w, fc2_w, rw);

    ln_kernel<<<M_, 256>>>(x, ln1_w, ln1_b, h1);
    tc_gemm<0><<<dim3(3*C_/128, M_/128), 256, GSMEM>>>(h1, rw + RW_QKV, nullptr, nullptr, qkvb, M_, 3*C_, C_);
    attn_mma<<<dim3(4, B_*H_), 256, ATT_SMEM>>>(qkvb, attn);
    tc_gemm<1><<<dim3(C_/128, M_/128), 256, GSMEM>>>(attn, rw + RW_PROJ, proj_b, nullptr, x2, M_, C_, C_);
    ln_kernel<<<M_, 256>>>(x2, ln2_w, ln2_b, ln2o);
    tc_gemm<2><<<dim3(HID_/128, M_/128), 256, GSMEM>>>(ln2o, rw + RW_FC1, fc1_b, nullptr, fc1o, M_, HID_, C_);
    tc_gemm<3><<<dim3(C_/128, M_/128), 256, GSMEM>>>(fc1o, rw + RW_FC2, fc2_b, x2, out, M_, C_, HID_);
}